// round 13
// baseline (speedup 1.0000x reference)
#include <cuda_runtime.h>
#include <cuda_bf16.h>
#include <cstdint>
#include <math.h>

#define T_TOK 16384
#define HDIM  4096
#define NEXP  64
#define TOPK  8
#define ALPHA 0.001f

#define BM 128
#define KC 32
#define NSTAGE 128
#define NTHREADS 256

#define AROW 36
#define A_ST (128 * AROW)
#define B_ST (64 * AROW)
#define SC_OFF ((3 * A_ST + 6 * B_ST) * 4)
#define SMEM_BYTES (SC_OFF + 128 * 66 * 4 + NEXP * 4)

typedef unsigned int u32;

__device__ float g_cnt[NEXP];
__device__ float g_psum[NEXP];
__device__ u32 g_whi[NEXP * HDIM];
__device__ u32 g_wlo[NEXP * HDIM];

__device__ __forceinline__ u32 s2u(const void* p) {
    u32 a;
    asm("{ .reg .u64 t; cvta.to.shared.u64 t, %1; cvt.u32.u64 %0, t; }" : "=r"(a) : "l"(p));
    return a;
}
__device__ __forceinline__ void cp16(u32 dst, const void* src) {
    asm volatile("cp.async.cg.shared.global [%0], [%1], 16;" :: "r"(dst), "l"(src));
}
__device__ __forceinline__ void cp_commit() { asm volatile("cp.async.commit_group;"); }
__device__ __forceinline__ void cp_wait1()  { asm volatile("cp.async.wait_group 1;"); }

__device__ __forceinline__ u32 f2tf(float x) {
    u32 r;
    asm("cvt.rna.tf32.f32 %0, %1;" : "=r"(r) : "f"(x));
    return r;
}

__device__ __forceinline__ void mma_tf32(float* c, u32 a0, u32 a1, u32 a2, u32 a3,
                                         u32 b0, u32 b1) {
    asm("mma.sync.aligned.m16n8k8.row.col.f32.tf32.tf32.f32 "
        "{%0,%1,%2,%3},{%4,%5,%6,%7},{%8,%9},{%0,%1,%2,%3};"
        : "+f"(c[0]), "+f"(c[1]), "+f"(c[2]), "+f"(c[3])
        : "r"(a0), "r"(a1), "r"(a2), "r"(a3), "r"(b0), "r"(b1));
}

__global__ void wconv_kernel(const float* __restrict__ w) {
    int i = blockIdx.x * 256 + threadIdx.x;
    float v = w[i];
    u32 hi = f2tf(v);
    u32 lo = f2tf(v - __uint_as_float(hi));
    g_whi[i] = hi;
    g_wlo[i] = lo;
}

extern __shared__ char smem_raw[];

__global__ __launch_bounds__(NTHREADS, 1)
void gate_kernel(const float* __restrict__ x,
                 float* __restrict__ out_w, float* __restrict__ out_i)
{
    u32* As = (u32*)smem_raw;           // fp32 raw, 3 stages
    u32* Bh = As + 3 * A_ST;            // tf32 hi, 3 stages
    u32* Bl = Bh + 3 * B_ST;            // tf32 lo, 3 stages
    float* sc   = (float*)(smem_raw + SC_OFF);
    float* cnts = sc + 128 * 66;

    const int tid = threadIdx.x;
    const int m0  = blockIdx.x * BM;
    if (tid < NEXP) cnts[tid] = 0.0f;

    const int wid  = tid >> 5;
    const int lane = tid & 31;
    const int wk = wid & 1;
    const int wn = (wid >> 1) & 1;
    const int wm = wid >> 2;
    const int g  = lane >> 2;
    const int cc4 = lane & 3;

    const int arow = tid >> 1;
    const int ach  = tid & 1;
    const float* xs = x + (size_t)(m0 + arow) * HDIM + ach * 16;
    const u32 adst = s2u(As + arow * AROW + ach * 16);

    const int brow = tid >> 2;
    const int bch  = tid & 3;
    const u32* whs = g_whi + brow * HDIM + bch * 4;
    const u32* wls = g_wlo + brow * HDIM + bch * 4;
    const u32 bhd = s2u(Bh + brow * AROW + bch * 4);
    const u32 bld = s2u(Bl + brow * AROW + bch * 4);

    // mma accumulators (short chains) + RN-accumulated sums
    float acc[4][4][4];
    float sum[4][4][4];
#pragma unroll
    for (int a = 0; a < 4; a++)
#pragma unroll
        for (int b = 0; b < 4; b++)
#pragma unroll
            for (int c = 0; c < 4; c++) { acc[a][b][c] = 0.0f; sum[a][b][c] = 0.0f; }

    // ---- prologue: stages 0,1 ----
#pragma unroll
    for (int st = 0; st < 2; st++) {
#pragma unroll
        for (int q = 0; q < 4; q++)
            cp16(adst + (st * A_ST + 4 * q) * 4, xs + st * KC + 4 * q);
        cp16(bhd + (st * B_ST) * 4,      whs + st * KC);
        cp16(bhd + (st * B_ST + 16) * 4, whs + st * KC + 16);
        cp16(bld + (st * B_ST) * 4,      wls + st * KC);
        cp16(bld + (st * B_ST + 16) * 4, wls + st * KC + 16);
        cp_commit();
    }

    for (int t = 0; t < NSTAGE; t++) {
        cp_wait1();
        __syncthreads();

        if (t + 2 < NSTAGE) {
            int sb = t + 2;
            int st = sb - (sb / 3) * 3;
#pragma unroll
            for (int q = 0; q < 4; q++)
                cp16(adst + (st * A_ST + 4 * q) * 4, xs + sb * KC + 4 * q);
            cp16(bhd + (st * B_ST) * 4,      whs + sb * KC);
            cp16(bhd + (st * B_ST + 16) * 4, whs + sb * KC + 16);
            cp16(bld + (st * B_ST) * 4,      wls + sb * KC);
            cp16(bld + (st * B_ST + 16) * 4, wls + sb * KC + 16);
        }
        cp_commit();

        int stc = t - (t / 3) * 3;
        const u32* Asb = As + stc * A_ST;
        const u32* Bhb = Bh + stc * B_ST;
        const u32* Blb = Bl + stc * B_ST;

#pragma unroll
        for (int s = 0; s < 2; s++) {
            const int kb = wk * 16 + s * 8 + cc4;

            u32 ah[4][4], al[4][4];
#pragma unroll
            for (int mt = 0; mt < 4; mt++) {
                const u32* p = Asb + (wm * 64 + mt * 16 + g) * AROW + kb;
                float f0 = __uint_as_float(p[0]);
                float f1 = __uint_as_float(p[8 * AROW]);
                float f2 = __uint_as_float(p[4]);
                float f3 = __uint_as_float(p[8 * AROW + 4]);
                ah[mt][0] = f2tf(f0); al[mt][0] = f2tf(f0 - __uint_as_float(ah[mt][0]));
                ah[mt][1] = f2tf(f1); al[mt][1] = f2tf(f1 - __uint_as_float(ah[mt][1]));
                ah[mt][2] = f2tf(f2); al[mt][2] = f2tf(f2 - __uint_as_float(ah[mt][2]));
                ah[mt][3] = f2tf(f3); al[mt][3] = f2tf(f3 - __uint_as_float(ah[mt][3]));
            }

            u32 bh[4][2], bl[4][2];
#pragma unroll
            for (int nt = 0; nt < 4; nt++) {
                const u32* ph = Bhb + (wn * 32 + nt * 8 + g) * AROW + kb;
                const u32* pl = Blb + (wn * 32 + nt * 8 + g) * AROW + kb;
                bh[nt][0] = ph[0]; bh[nt][1] = ph[4];
                bl[nt][0] = pl[0]; bl[nt][1] = pl[4];
            }

#pragma unroll
            for (int mt = 0; mt < 4; mt++)
#pragma unroll
                for (int nt = 0; nt < 4; nt++) {
                    mma_tf32(acc[mt][nt], ah[mt][0], ah[mt][1], ah[mt][2], ah[mt][3],
                             bh[nt][0], bh[nt][1]);
                    mma_tf32(acc[mt][nt], ah[mt][0], ah[mt][1], ah[mt][2], ah[mt][3],
                             bl[nt][0], bl[nt][1]);
                    mma_tf32(acc[mt][nt], al[mt][0], al[mt][1], al[mt][2], al[mt][3],
                             bh[nt][0], bh[nt][1]);
                }
        }

        // drain mma accumulators every 2 stages: kills the tensor-core
        // RZ accumulation bias (chain length 4 instead of 256)
        if ((t & 1) == 1) {
#pragma unroll
            for (int mt = 0; mt < 4; mt++)
#pragma unroll
                for (int nt = 0; nt < 4; nt++)
#pragma unroll
                    for (int c = 0; c < 4; c++) {
                        sum[mt][nt][c] += acc[mt][nt][c];
                        acc[mt][nt][c] = 0.0f;
                    }
        }
    }

    // ---- k-split reduction into sc ----
    const int c2 = cc4 * 2;
    __syncthreads();
    if (wk == 0) {
#pragma unroll
        for (int mt = 0; mt < 4; mt++)
#pragma unroll
            for (int nt = 0; nt < 4; nt++) {
                int r0 = wm * 64 + mt * 16 + g;
                int cn = wn * 32 + nt * 8 + c2;
                *(float2*)&sc[r0 * 66 + cn]       = make_float2(sum[mt][nt][0], sum[mt][nt][1]);
                *(float2*)&sc[(r0 + 8) * 66 + cn] = make_float2(sum[mt][nt][2], sum[mt][nt][3]);
            }
    }
    __syncthreads();
    if (wk == 1) {
#pragma unroll
        for (int mt = 0; mt < 4; mt++)
#pragma unroll
            for (int nt = 0; nt < 4; nt++) {
                int r0 = wm * 64 + mt * 16 + g;
                int cn = wn * 32 + nt * 8 + c2;
                float2* p0 = (float2*)&sc[r0 * 66 + cn];
                float2* p1 = (float2*)&sc[(r0 + 8) * 66 + cn];
                float2 v0 = *p0, v1 = *p1;
                v0.x += sum[mt][nt][0]; v0.y += sum[mt][nt][1];
                v1.x += sum[mt][nt][2]; v1.y += sum[mt][nt][3];
                *p0 = v0; *p1 = v1;
            }
    }
    __syncthreads();

    // ---- softmax + top-8: 8 warps x 16 tokens ----
    for (int t = wid * 16; t < wid * 16 + 16; t++) {
        float v0 = sc[t * 66 + lane];
        float v1 = sc[t * 66 + lane + 32];
        float mx = fmaxf(v0, v1);
#pragma unroll
        for (int off = 16; off > 0; off >>= 1)
            mx = fmaxf(mx, __shfl_xor_sync(0xFFFFFFFFu, mx, off));
        float e0 = expf(v0 - mx);
        float e1 = expf(v1 - mx);
        float s = e0 + e1;
#pragma unroll
        for (int off = 16; off > 0; off >>= 1)
            s += __shfl_xor_sync(0xFFFFFFFFu, s, off);
        float inv = 1.0f / s;
        float s0 = e0 * inv;
        float s1 = e1 * inv;
        sc[t * 66 + lane]      = s0;
        sc[t * 66 + lane + 32] = s1;

        float r0 = s0, r1 = s1;
#pragma unroll
        for (int r = 0; r < TOPK; r++) {
            float bv; int bi;
            if (r0 >= r1) { bv = r0; bi = lane; }
            else          { bv = r1; bi = lane + 32; }
#pragma unroll
            for (int off = 16; off > 0; off >>= 1) {
                float ov = __shfl_xor_sync(0xFFFFFFFFu, bv, off);
                int   oi = __shfl_xor_sync(0xFFFFFFFFu, bi, off);
                if (ov > bv || (ov == bv && oi < bi)) { bv = ov; bi = oi; }
            }
            if (lane == 0) {
                out_w[(size_t)(m0 + t) * TOPK + r] = bv;
                out_i[(size_t)(m0 + t) * TOPK + r] = (float)bi;
                atomicAdd(&cnts[bi], 1.0f);
            }
            if (bi == lane)           r0 = -1.0f;
            else if (bi == lane + 32) r1 = -1.0f;
        }
    }
    __syncthreads();

    if (tid < NEXP) {
        float s = 0.0f;
#pragma unroll 8
        for (int t = 0; t < BM; t++) s += sc[t * 66 + tid];
        atomicAdd(&g_psum[tid], s);
        atomicAdd(&g_cnt[tid],  cnts[tid]);
    }
}

__global__ void finalize_kernel(float* __restrict__ out)
{
    __shared__ float red[NEXP];
    int e = threadIdx.x;
    float Pi = g_psum[e] / (float)T_TOK;
    float fi = g_cnt[e] / ((float)T_TOK * (float)TOPK) * (float)NEXP;
    red[e] = Pi * fi;
    __syncthreads();
    if (e < 32) {
        float v = red[e] + red[e + 32];
#pragma unroll
        for (int off = 16; off > 0; off >>= 1)
            v += __shfl_xor_sync(0xFFFFFFFFu, v, off);
        if (e == 0)
            out[(size_t)2 * T_TOK * TOPK] = v * ALPHA;
    }
}

extern "C" void kernel_launch(void* const* d_in, const int* in_sizes, int n_in,
                              void* d_out, int out_size)
{
    const float* hs = (const float*)d_in[0];
    const float* w  = (const float*)d_in[1];
    float* out  = (float*)d_out;
    float* outw = out;
    float* outi = out + (size_t)T_TOK * TOPK;

    cudaFuncSetAttribute(gate_kernel, cudaFuncAttributeMaxDynamicSharedMemorySize, SMEM_BYTES);

    void *cptr = nullptr, *pptr = nullptr;
    cudaGetSymbolAddress(&cptr, g_cnt);
    cudaGetSymbolAddress(&pptr, g_psum);
    cudaMemsetAsync(cptr, 0, NEXP * sizeof(float));
    cudaMemsetAsync(pptr, 0, NEXP * sizeof(float));

    wconv_kernel<<<NEXP * HDIM / 256, 256>>>(w);
    gate_kernel<<<T_TOK / BM, NTHREADS, SMEM_BYTES>>>(hs, outw, outi);
    finalize_kernel<<<1, NEXP>>>(out);
}

// round 14
// speedup vs baseline: 1.0038x; 1.0038x over previous
#include <cuda_runtime.h>
#include <cuda_bf16.h>
#include <cstdint>
#include <math.h>

#define T_TOK 16384
#define HDIM  4096
#define NEXP  64
#define TOPK  8
#define ALPHA 0.001f

#define BM 128
#define KC 32
#define NSTAGE 128
#define NTHREADS 256

#define AROW 36
#define A_ST (128 * AROW)
#define B_ST (64 * AROW)
#define SC_OFF ((3 * A_ST + 6 * B_ST) * 4)
#define SMEM_BYTES (SC_OFF + 128 * 66 * 4 + NEXP * 4)

typedef unsigned int u32;

__device__ float g_cnt[NEXP];
__device__ float g_psum[NEXP];
__device__ u32 g_whi[NEXP * HDIM];
__device__ u32 g_wlo[NEXP * HDIM];

__device__ __forceinline__ u32 s2u(const void* p) {
    u32 a;
    asm("{ .reg .u64 t; cvta.to.shared.u64 t, %1; cvt.u32.u64 %0, t; }" : "=r"(a) : "l"(p));
    return a;
}
__device__ __forceinline__ void cp16(u32 dst, const void* src) {
    asm volatile("cp.async.cg.shared.global [%0], [%1], 16;" :: "r"(dst), "l"(src));
}
__device__ __forceinline__ void cp_commit() { asm volatile("cp.async.commit_group;"); }
__device__ __forceinline__ void cp_wait1()  { asm volatile("cp.async.wait_group 1;"); }

__device__ __forceinline__ u32 f2tf(float x) {
    u32 r;
    asm("cvt.rna.tf32.f32 %0, %1;" : "=r"(r) : "f"(x));
    return r;
}

__device__ __forceinline__ void mma_tf32(float* c, u32 a0, u32 a1, u32 a2, u32 a3,
                                         u32 b0, u32 b1) {
    asm("mma.sync.aligned.m16n8k8.row.col.f32.tf32.tf32.f32 "
        "{%0,%1,%2,%3},{%4,%5,%6,%7},{%8,%9},{%0,%1,%2,%3};"
        : "+f"(c[0]), "+f"(c[1]), "+f"(c[2]), "+f"(c[3])
        : "r"(a0), "r"(a1), "r"(a2), "r"(a3), "r"(b0), "r"(b1));
}

__global__ void wconv_kernel(const float* __restrict__ w) {
    int i = blockIdx.x * 256 + threadIdx.x;
    float v = w[i];
    u32 hi = f2tf(v);
    u32 lo = f2tf(v - __uint_as_float(hi));
    g_whi[i] = hi;
    g_wlo[i] = lo;
}

extern __shared__ char smem_raw[];

__global__ __launch_bounds__(NTHREADS, 1)
void gate_kernel(const float* __restrict__ x,
                 float* __restrict__ out_w, float* __restrict__ out_i)
{
    u32* As = (u32*)smem_raw;           // fp32 raw, 3 stages
    u32* Bh = As + 3 * A_ST;            // tf32 hi, 3 stages
    u32* Bl = Bh + 3 * B_ST;            // tf32 lo, 3 stages
    float* sc   = (float*)(smem_raw + SC_OFF);
    float* cnts = sc + 128 * 66;

    const int tid = threadIdx.x;
    const int m0  = blockIdx.x * BM;
    if (tid < NEXP) cnts[tid] = 0.0f;

    const int wid  = tid >> 5;
    const int lane = tid & 31;
    const int wk = wid & 1;
    const int wn = (wid >> 1) & 1;
    const int wm = wid >> 2;
    const int g  = lane >> 2;
    const int cc4 = lane & 3;

    const int arow = tid >> 1;
    const int ach  = tid & 1;
    const float* xs = x + (size_t)(m0 + arow) * HDIM + ach * 16;
    const u32 adst = s2u(As + arow * AROW + ach * 16);

    const int brow = tid >> 2;
    const int bch  = tid & 3;
    const u32* whs = g_whi + brow * HDIM + bch * 4;
    const u32* wls = g_wlo + brow * HDIM + bch * 4;
    const u32 bhd = s2u(Bh + brow * AROW + bch * 4);
    const u32 bld = s2u(Bl + brow * AROW + bch * 4);

    // mma accumulators (short chains) + RN-accumulated sums
    float acc[4][4][4];
    float sum[4][4][4];
#pragma unroll
    for (int a = 0; a < 4; a++)
#pragma unroll
        for (int b = 0; b < 4; b++)
#pragma unroll
            for (int c = 0; c < 4; c++) { acc[a][b][c] = 0.0f; sum[a][b][c] = 0.0f; }

    // ---- prologue: stages 0,1 ----
#pragma unroll
    for (int st = 0; st < 2; st++) {
#pragma unroll
        for (int q = 0; q < 4; q++)
            cp16(adst + (st * A_ST + 4 * q) * 4, xs + st * KC + 4 * q);
        cp16(bhd + (st * B_ST) * 4,      whs + st * KC);
        cp16(bhd + (st * B_ST + 16) * 4, whs + st * KC + 16);
        cp16(bld + (st * B_ST) * 4,      wls + st * KC);
        cp16(bld + (st * B_ST + 16) * 4, wls + st * KC + 16);
        cp_commit();
    }

    for (int t = 0; t < NSTAGE; t++) {
        cp_wait1();
        __syncthreads();

        if (t + 2 < NSTAGE) {
            int sb = t + 2;
            int st = sb - (sb / 3) * 3;
#pragma unroll
            for (int q = 0; q < 4; q++)
                cp16(adst + (st * A_ST + 4 * q) * 4, xs + sb * KC + 4 * q);
            cp16(bhd + (st * B_ST) * 4,      whs + sb * KC);
            cp16(bhd + (st * B_ST + 16) * 4, whs + sb * KC + 16);
            cp16(bld + (st * B_ST) * 4,      wls + sb * KC);
            cp16(bld + (st * B_ST + 16) * 4, wls + sb * KC + 16);
        }
        cp_commit();

        int stc = t - (t / 3) * 3;
        const u32* Asb = As + stc * A_ST;
        const u32* Bhb = Bh + stc * B_ST;
        const u32* Blb = Bl + stc * B_ST;

#pragma unroll
        for (int s = 0; s < 2; s++) {
            const int kb = wk * 16 + s * 8 + cc4;

            u32 ah[4][4], al[4][4];
#pragma unroll
            for (int mt = 0; mt < 4; mt++) {
                const u32* p = Asb + (wm * 64 + mt * 16 + g) * AROW + kb;
                float f0 = __uint_as_float(p[0]);
                float f1 = __uint_as_float(p[8 * AROW]);
                float f2 = __uint_as_float(p[4]);
                float f3 = __uint_as_float(p[8 * AROW + 4]);
                ah[mt][0] = f2tf(f0); al[mt][0] = f2tf(f0 - __uint_as_float(ah[mt][0]));
                ah[mt][1] = f2tf(f1); al[mt][1] = f2tf(f1 - __uint_as_float(ah[mt][1]));
                ah[mt][2] = f2tf(f2); al[mt][2] = f2tf(f2 - __uint_as_float(ah[mt][2]));
                ah[mt][3] = f2tf(f3); al[mt][3] = f2tf(f3 - __uint_as_float(ah[mt][3]));
            }

            u32 bh[4][2], bl[4][2];
#pragma unroll
            for (int nt = 0; nt < 4; nt++) {
                const u32* ph = Bhb + (wn * 32 + nt * 8 + g) * AROW + kb;
                const u32* pl = Blb + (wn * 32 + nt * 8 + g) * AROW + kb;
                bh[nt][0] = ph[0]; bh[nt][1] = ph[4];
                bl[nt][0] = pl[0]; bl[nt][1] = pl[4];
            }

#pragma unroll
            for (int mt = 0; mt < 4; mt++)
#pragma unroll
                for (int nt = 0; nt < 4; nt++) {
                    mma_tf32(acc[mt][nt], ah[mt][0], ah[mt][1], ah[mt][2], ah[mt][3],
                             bh[nt][0], bh[nt][1]);
                    mma_tf32(acc[mt][nt], ah[mt][0], ah[mt][1], ah[mt][2], ah[mt][3],
                             bl[nt][0], bl[nt][1]);
                    mma_tf32(acc[mt][nt], al[mt][0], al[mt][1], al[mt][2], al[mt][3],
                             bh[nt][0], bh[nt][1]);
                }
        }

        // drain mma accumulators every 2 stages: kills the tensor-core
        // RZ accumulation bias (chain length 4 instead of 256)
        if ((t & 1) == 1) {
#pragma unroll
            for (int mt = 0; mt < 4; mt++)
#pragma unroll
                for (int nt = 0; nt < 4; nt++)
#pragma unroll
                    for (int c = 0; c < 4; c++) {
                        sum[mt][nt][c] += acc[mt][nt][c];
                        acc[mt][nt][c] = 0.0f;
                    }
        }
    }

    // ---- k-split reduction into sc ----
    const int c2 = cc4 * 2;
    __syncthreads();
    if (wk == 0) {
#pragma unroll
        for (int mt = 0; mt < 4; mt++)
#pragma unroll
            for (int nt = 0; nt < 4; nt++) {
                int r0 = wm * 64 + mt * 16 + g;
                int cn = wn * 32 + nt * 8 + c2;
                *(float2*)&sc[r0 * 66 + cn]       = make_float2(sum[mt][nt][0], sum[mt][nt][1]);
                *(float2*)&sc[(r0 + 8) * 66 + cn] = make_float2(sum[mt][nt][2], sum[mt][nt][3]);
            }
    }
    __syncthreads();
    if (wk == 1) {
#pragma unroll
        for (int mt = 0; mt < 4; mt++)
#pragma unroll
            for (int nt = 0; nt < 4; nt++) {
                int r0 = wm * 64 + mt * 16 + g;
                int cn = wn * 32 + nt * 8 + c2;
                float2* p0 = (float2*)&sc[r0 * 66 + cn];
                float2* p1 = (float2*)&sc[(r0 + 8) * 66 + cn];
                float2 v0 = *p0, v1 = *p1;
                v0.x += sum[mt][nt][0]; v0.y += sum[mt][nt][1];
                v1.x += sum[mt][nt][2]; v1.y += sum[mt][nt][3];
                *p0 = v0; *p1 = v1;
            }
    }
    __syncthreads();

    // ---- softmax + top-8: 8 warps x 16 tokens ----
    for (int t = wid * 16; t < wid * 16 + 16; t++) {
        float v0 = sc[t * 66 + lane];
        float v1 = sc[t * 66 + lane + 32];
        float mx = fmaxf(v0, v1);
#pragma unroll
        for (int off = 16; off > 0; off >>= 1)
            mx = fmaxf(mx, __shfl_xor_sync(0xFFFFFFFFu, mx, off));
        float e0 = expf(v0 - mx);
        float e1 = expf(v1 - mx);
        float s = e0 + e1;
#pragma unroll
        for (int off = 16; off > 0; off >>= 1)
            s += __shfl_xor_sync(0xFFFFFFFFu, s, off);
        float inv = 1.0f / s;
        float s0 = e0 * inv;
        float s1 = e1 * inv;
        sc[t * 66 + lane]      = s0;
        sc[t * 66 + lane + 32] = s1;

        float r0 = s0, r1 = s1;
#pragma unroll
        for (int r = 0; r < TOPK; r++) {
            float bv; int bi;
            if (r0 >= r1) { bv = r0; bi = lane; }
            else          { bv = r1; bi = lane + 32; }
#pragma unroll
            for (int off = 16; off > 0; off >>= 1) {
                float ov = __shfl_xor_sync(0xFFFFFFFFu, bv, off);
                int   oi = __shfl_xor_sync(0xFFFFFFFFu, bi, off);
                if (ov > bv || (ov == bv && oi < bi)) { bv = ov; bi = oi; }
            }
            if (lane == 0) {
                out_w[(size_t)(m0 + t) * TOPK + r] = bv;
                out_i[(size_t)(m0 + t) * TOPK + r] = (float)bi;
                atomicAdd(&cnts[bi], 1.0f);
            }
            if (bi == lane)           r0 = -1.0f;
            else if (bi == lane + 32) r1 = -1.0f;
        }
    }
    __syncthreads();

    if (tid < NEXP) {
        float s = 0.0f;
#pragma unroll 8
        for (int t = 0; t < BM; t++) s += sc[t * 66 + tid];
        atomicAdd(&g_psum[tid], s);
        atomicAdd(&g_cnt[tid],  cnts[tid]);
    }
}

__global__ void finalize_kernel(float* __restrict__ out)
{
    __shared__ float red[NEXP];
    int e = threadIdx.x;
    float Pi = g_psum[e] / (float)T_TOK;
    float fi = g_cnt[e] / ((float)T_TOK * (float)TOPK) * (float)NEXP;
    red[e] = Pi * fi;
    __syncthreads();
    if (e < 32) {
        float v = red[e] + red[e + 32];
#pragma unroll
        for (int off = 16; off > 0; off >>= 1)
            v += __shfl_xor_sync(0xFFFFFFFFu, v, off);
        if (e == 0)
            out[(size_t)2 * T_TOK * TOPK] = v * ALPHA;
    }
}

extern "C" void kernel_launch(void* const* d_in, const int* in_sizes, int n_in,
                              void* d_out, int out_size)
{
    const float* hs = (const float*)d_in[0];
    const float* w  = (const float*)d_in[1];
    float* out  = (float*)d_out;
    float* outw = out;
    float* outi = out + (size_t)T_TOK * TOPK;

    cudaFuncSetAttribute(gate_kernel, cudaFuncAttributeMaxDynamicSharedMemorySize, SMEM_BYTES);

    void *cptr = nullptr, *pptr = nullptr;
    cudaGetSymbolAddress(&cptr, g_cnt);
    cudaGetSymbolAddress(&pptr, g_psum);
    cudaMemsetAsync(cptr, 0, NEXP * sizeof(float));
    cudaMemsetAsync(pptr, 0, NEXP * sizeof(float));

    wconv_kernel<<<NEXP * HDIM / 256, 256>>>(w);
    gate_kernel<<<T_TOK / BM, NTHREADS, SMEM_BYTES>>>(hs, outw, outi);
    finalize_kernel<<<1, NEXP>>>(out);
}